// round 4
// baseline (speedup 1.0000x reference)
#include <cuda_runtime.h>
#include <cstdint>
#include <cstddef>

// 1x1 conv as GEMM on HMMA (mma.sync tf32), sm_103 (no tcgen05 in this toolchain path).
// out[b,o,p] = sum_i W[i,o] * x[b,i,p];  B=32, CIN=COUT=128, HW=16384.
// R4: B (x) fragments loaded DIRECTLY from global (sector-aligned), no B smem,
// no per-tile barriers. SMEM holds only W^T (69.6KB) -> 2 CTAs/SM, 16 warps.
// Persistent: 304 CTAs, ~13-14 tiles each. Tile: M=128(COUT) x N=128(px) x K=128.
// 8 warps: 2(M) x 4(N), warp tile m64 x n32, mma.m16n8k8.tf32, 1-kstep B prefetch.

#define HW      16384
#define NCH     128
#define TILE_N  128
#define NTILES  4096
#define GRID    304
#define NTHREADS 256
#define ROWW    136                       // padded A row width in floats
#define SMEM_BYTES (NCH * ROWW * 4)       // 69632

__device__ __forceinline__ uint32_t smem_u32(const void* p) {
    uint32_t a;
    asm("{ .reg .u64 t; cvta.to.shared.u64 t, %1; cvt.u32.u64 %0, t; }" : "=r"(a) : "l"(p));
    return a;
}

__device__ __forceinline__ void mma_tf32(float c[4], uint32_t a0, uint32_t a1,
                                         uint32_t a2, uint32_t a3,
                                         uint32_t b0, uint32_t b1) {
    asm volatile(
        "mma.sync.aligned.m16n8k8.row.col.f32.tf32.tf32.f32 "
        "{%0,%1,%2,%3},{%4,%5,%6,%7},{%8,%9},{%0,%1,%2,%3};"
        : "+f"(c[0]), "+f"(c[1]), "+f"(c[2]), "+f"(c[3])
        : "r"(a0), "r"(a1), "r"(a2), "r"(a3), "r"(b0), "r"(b1));
}

__global__ __launch_bounds__(NTHREADS, 2)
void conv1x1_hmma_kernel(const float* __restrict__ x,
                         const float* __restrict__ w,
                         float* __restrict__ out)
{
    extern __shared__ __align__(16) float smem[];    // A = W^T only
    const int tid = threadIdx.x;
    const int lid = tid & 31;
    const int wid = tid >> 5;
    const int mw  = wid & 1;          // M half (0..1)
    const int nw  = wid >> 1;         // N quarter (0..3)
    const int bid = blockIdx.x;
    const int lr  = lid >> 2;         // 0..7
    const int lc  = lid & 3;          // 0..3

    // ---- W^T -> smem once, RN-rounded to tf32, k-pair-interleaved layout:
    // word(o,k) = o*ROWW + (k/8)*8 + (k%4)*2 + ((k/4)&1)
    for (int i = tid; i < NCH * NCH; i += NTHREADS) {
        int k = i >> 7, o = i & 127;
        float v = __ldg(&w[k * NCH + o]);
        uint32_t t;
        asm("cvt.rna.tf32.f32 %0, %1;" : "=r"(t) : "f"(v));
        smem[o * ROWW + (k >> 3) * 8 + (k & 3) * 2 + ((k >> 2) & 1)] = __uint_as_float(t);
    }
    __syncthreads();

    const int n = (NTILES - bid + GRID - 1) / GRID;

    // Per-lane global B base for a tile t: row k = lc (+4 stride), col p0+nw*32+lr (+nt*8)
    auto make_pB = [&](int t) -> const float* {
        int b = t >> 7, p0 = (t & 127) * TILE_N;
        return x + ((size_t)b * NCH + lc) * HW + p0 + nw * 32 + lr;
    };

    uint32_t bq[2][8];
    // load8: B fragments of k-step kk into dst
    auto load8 = [&](uint32_t* dst, const float* pB, int kk) {
        const float* r0 = pB + (size_t)(kk * 8) * HW;
        #pragma unroll
        for (int nt = 0; nt < 4; nt++) {
            dst[nt * 2 + 0] = __float_as_uint(__ldg(r0 + nt * 8));
            dst[nt * 2 + 1] = __float_as_uint(__ldg(r0 + 4 * HW + nt * 8));
        }
    };

    int t = bid;
    const float* pB = make_pB(t);
    load8(bq[0], pB, 0);

    const float* Asm = smem + (mw * 64 + lr) * ROWW + lc * 2;

    #pragma unroll 1
    for (int i = 0; i < n; i++) {
        float acc[4][4][4];
        #pragma unroll
        for (int mt = 0; mt < 4; mt++)
            #pragma unroll
            for (int nt = 0; nt < 4; nt++)
                #pragma unroll
                for (int q = 0; q < 4; q++) acc[mt][nt][q] = 0.f;

        const float* pBn = pB;

        #pragma unroll
        for (int kk = 0; kk < 16; kk++) {
            // prefetch next k-step (crosses into next tile at kk==15)
            if (kk < 15) {
                load8(bq[(kk + 1) & 1], pB, kk + 1);
            } else if (i + 1 < n) {
                pBn = make_pB(t + GRID);
                load8(bq[0], pBn, 0);
            }

            uint32_t af[4][4];
            #pragma unroll
            for (int mt = 0; mt < 4; mt++) {
                const float* pa = Asm + mt * 16 * ROWW + kk * 8;
                asm volatile("ld.shared.v2.b32 {%0,%1}, [%2];"
                    : "=r"(af[mt][0]), "=r"(af[mt][2]) : "r"(smem_u32(pa)));
                asm volatile("ld.shared.v2.b32 {%0,%1}, [%2];"
                    : "=r"(af[mt][1]), "=r"(af[mt][3]) : "r"(smem_u32(pa + 8 * ROWW)));
            }

            const uint32_t* bf = bq[kk & 1];
            #pragma unroll
            for (int mt = 0; mt < 4; mt++)
                #pragma unroll
                for (int nt = 0; nt < 4; nt++)
                    mma_tf32(acc[mt][nt], af[mt][0], af[mt][1], af[mt][2], af[mt][3],
                             bf[nt * 2], bf[nt * 2 + 1]);
        }

        // ---- epilogue: store 64x32 warp tile
        {
            int b = t >> 7, p0 = (t & 127) * TILE_N;
            float* ob = out + (size_t)b * NCH * HW + p0 + nw * 32 + lc * 2;
            #pragma unroll
            for (int mt = 0; mt < 4; mt++) {
                float* orow = ob + (size_t)(mw * 64 + mt * 16 + lr) * HW;
                #pragma unroll
                for (int nt = 0; nt < 4; nt++) {
                    *(float2*)(orow + nt * 8)          = make_float2(acc[mt][nt][0], acc[mt][nt][1]);
                    *(float2*)(orow + 8 * HW + nt * 8) = make_float2(acc[mt][nt][2], acc[mt][nt][3]);
                }
            }
        }

        t += GRID;
        pB = pBn;
    }
}

extern "C" void kernel_launch(void* const* d_in, const int* in_sizes, int n_in,
                              void* d_out, int out_size)
{
    const float* x = (const float*)d_in[0];   // (32,128,128,128) fp32
    const float* w = (const float*)d_in[1];   // (128,128) fp32
    float* out = (float*)d_out;

    cudaFuncSetAttribute(conv1x1_hmma_kernel,
                         cudaFuncAttributeMaxDynamicSharedMemorySize, SMEM_BYTES);
    conv1x1_hmma_kernel<<<GRID, NTHREADS, SMEM_BYTES>>>(x, w, out);
}

// round 5
// speedup vs baseline: 1.1906x; 1.1906x over previous
#include <cuda_runtime.h>
#include <cstdint>
#include <cstddef>

// 1x1 conv as GEMM on HMMA (mma.sync tf32), sm_103 target (tcgen05 unavailable
// in this toolchain's compute_103 PTX path).
// out[b,o,p] = sum_i W[i,o] * x[b,i,p];  B=32, CIN=COUT=128, HW=16384.
// R5: R3 structure (cp.async staged B, smem A) but B staged in K-CHUNKS of 32
// rows (16KB, XOR-swizzled, double-buffered) -> smem 100KB -> 2 CTAs/SM.
// Tile: M=128(COUT) x N=128(px) x K=128. 8 warps 2(M)x4(N), warp m64n32,
// mma.m16n8k8.tf32.

#define HW      16384
#define NCH     128
#define TILE_N  128
#define NTILES  4096
#define GRID    304
#define NTHREADS 256
#define ROWW    136                 // padded A row width (floats)

#define A_OFF   0                   // 128*136 = 17408 floats
#define B_OFF   17408               // 2 chunks x 32x128 floats
#define SMEM_FLOATS (17408 + 2 * 4096)
#define SMEM_BYTES  (SMEM_FLOATS * 4)   // 102400 B

__device__ __forceinline__ uint32_t smem_u32(const void* p) {
    uint32_t a;
    asm("{ .reg .u64 t; cvta.to.shared.u64 t, %1; cvt.u32.u64 %0, t; }" : "=r"(a) : "l"(p));
    return a;
}

#define CP_ASYNC16(smaddr, gptr) \
    asm volatile("cp.async.cg.shared.global [%0], [%1], 16;" \
        :: "r"(smaddr), "l"(__cvta_generic_to_global(gptr)) : "memory")
#define CP_COMMIT() asm volatile("cp.async.commit_group;" ::: "memory")
#define CP_WAIT(n)  asm volatile("cp.async.wait_group %0;" :: "n"(n) : "memory")

__device__ __forceinline__ void mma_tf32(float c[4], uint32_t a0, uint32_t a1,
                                         uint32_t a2, uint32_t a3,
                                         uint32_t b0, uint32_t b1) {
    asm volatile(
        "mma.sync.aligned.m16n8k8.row.col.f32.tf32.tf32.f32 "
        "{%0,%1,%2,%3},{%4,%5,%6,%7},{%8,%9},{%0,%1,%2,%3};"
        : "+f"(c[0]), "+f"(c[1]), "+f"(c[2]), "+f"(c[3])
        : "r"(a0), "r"(a1), "r"(a2), "r"(a3), "r"(b0), "r"(b1));
}

__global__ __launch_bounds__(NTHREADS, 2)
void conv1x1_hmma_kernel(const float* __restrict__ x,
                         const float* __restrict__ w,
                         float* __restrict__ out)
{
    extern __shared__ __align__(16) float smem[];
    const uint32_t sb = smem_u32(smem);
    const int tid = threadIdx.x;
    const int lid = tid & 31;
    const int wid = tid >> 5;
    const int mw  = wid & 1;          // M half
    const int nw  = wid >> 1;         // N quarter
    const int bid = blockIdx.x;
    const int lr  = lid >> 2;         // 0..7
    const int lc  = lid & 3;          // 0..3

    // ---- W^T -> A smem once, RN-rounded tf32, k-pair-interleaved:
    // word(o,k) = o*ROWW + (k/8)*8 + (k%4)*2 + ((k/4)&1)
    for (int i = tid; i < NCH * NCH; i += NTHREADS) {
        int k = i >> 7, o = i & 127;
        float v = __ldg(&w[k * NCH + o]);
        uint32_t t;
        asm("cvt.rna.tf32.f32 %0, %1;" : "=r"(t) : "f"(v));
        smem[A_OFF + o * ROWW + (k >> 3) * 8 + (k & 3) * 2 + ((k >> 2) & 1)] = __uint_as_float(t);
    }
    __syncthreads();

    const int n = (NTILES - bid + GRID - 1) / GRID;
    const int total = 4 * n;                    // chunks of 32 k-rows

    // ---- B chunk loader: 32 k-rows x 128 px, swizzle col ^= (row&3)<<3
    auto load_chunk = [&](int cc) {
        int t  = bid + (cc >> 2) * GRID;
        int b  = t >> 7;
        int p0 = (t & 127) * TILE_N;
        int k0 = (cc & 3) * 32;
        const float* xb = x + ((size_t)b * NCH + k0) * HW + p0;
        uint32_t base = sb + (uint32_t)(B_OFF + (cc & 1) * 4096) * 4u;
        #pragma unroll
        for (int j = 0; j < 4; j++) {
            int id  = tid + j * NTHREADS;       // 0..1023
            int row = id >> 5;                  // 0..31
            int px4 = (id & 31) * 4;            // 0..124
            uint32_t wd = (uint32_t)(row * 128 + (px4 ^ ((row & 3) << 3)));
            CP_ASYNC16(base + wd * 4u, xb + (size_t)row * HW + px4);
        }
    };

    load_chunk(0); CP_COMMIT();

    const float* Asm = smem + A_OFF + (mw * 64 + lr) * ROWW + lc * 2;
    float acc[4][4][4];

    #pragma unroll 1
    for (int cc = 0; cc < total; cc++) {
        if (cc + 1 < total) { load_chunk(cc + 1); CP_COMMIT(); CP_WAIT(1); }
        else                { CP_WAIT(0); }
        __syncthreads();

        if ((cc & 3) == 0) {
            #pragma unroll
            for (int mt = 0; mt < 4; mt++)
                #pragma unroll
                for (int nt = 0; nt < 4; nt++)
                    #pragma unroll
                    for (int q = 0; q < 4; q++) acc[mt][nt][q] = 0.f;
        }

        const float* Bs = smem + B_OFF + (cc & 1) * 4096 + nw * 32 + lr;
        const int kk0 = (cc & 3) * 4;

        #pragma unroll
        for (int kl = 0; kl < 4; kl++) {
            const int kk = kk0 + kl;
            uint32_t af[4][4];
            #pragma unroll
            for (int mt = 0; mt < 4; mt++) {
                const float* pa = Asm + mt * 16 * ROWW + kk * 8;
                asm volatile("ld.shared.v2.b32 {%0,%1}, [%2];"
                    : "=r"(af[mt][0]), "=r"(af[mt][2]) : "r"(smem_u32(pa)));
                asm volatile("ld.shared.v2.b32 {%0,%1}, [%2];"
                    : "=r"(af[mt][1]), "=r"(af[mt][3]) : "r"(smem_u32(pa + 8 * ROWW)));
            }
            uint32_t bf[4][2];
            const float* pb = Bs + (kl * 8 + lc) * 128;
            #pragma unroll
            for (int nt = 0; nt < 4; nt++) {
                int sw = (nt ^ lc) * 8;         // swizzled column block
                bf[nt][0] = __float_as_uint(pb[sw]);
                bf[nt][1] = __float_as_uint(pb[4 * 128 + sw]);
            }
            #pragma unroll
            for (int mt = 0; mt < 4; mt++)
                #pragma unroll
                for (int nt = 0; nt < 4; nt++)
                    mma_tf32(acc[mt][nt], af[mt][0], af[mt][1], af[mt][2], af[mt][3],
                             bf[nt][0], bf[nt][1]);
        }

        if ((cc & 3) == 3) {                    // tile finished -> epilogue
            int t  = bid + (cc >> 2) * GRID;
            int b  = t >> 7;
            int p0 = (t & 127) * TILE_N;
            float* ob = out + (size_t)b * NCH * HW + p0 + nw * 32 + lc * 2;
            #pragma unroll
            for (int mt = 0; mt < 4; mt++) {
                float* orow = ob + (size_t)(mw * 64 + mt * 16 + lr) * HW;
                #pragma unroll
                for (int nt = 0; nt < 4; nt++) {
                    *(float2*)(orow + nt * 8)          = make_float2(acc[mt][nt][0], acc[mt][nt][1]);
                    *(float2*)(orow + 8 * HW + nt * 8) = make_float2(acc[mt][nt][2], acc[mt][nt][3]);
                }
            }
        }
        __syncthreads();                        // buf (cc&1) free for load(cc+2)
    }
}

extern "C" void kernel_launch(void* const* d_in, const int* in_sizes, int n_in,
                              void* d_out, int out_size)
{
    const float* x = (const float*)d_in[0];   // (32,128,128,128) fp32
    const float* w = (const float*)d_in[1];   // (128,128) fp32
    float* out = (float*)d_out;

    cudaFuncSetAttribute(conv1x1_hmma_kernel,
                         cudaFuncAttributeMaxDynamicSharedMemorySize, SMEM_BYTES);
    conv1x1_hmma_kernel<<<GRID, NTHREADS, SMEM_BYTES>>>(x, w, out);
}